// round 14
// baseline (speedup 1.0000x reference)
#include <cuda_runtime.h>
#include <cuda_fp16.h>
#include <math.h>
#include <stdint.h>

#define T_TOKENS 4096
#define D_DIM    768
#define F_DIM    3072
#define E_EXP    8
#define EXP_CAP  4096
#define NSLOTS   (E_EXP * EXP_CAP)

// ------------------------------------------------------------------ scratch
__device__ int   g_fill[E_EXP];          // zeroed by memset each call
__device__ int   g_slot_token[NSLOTS];
__device__ float g_slot_w[NSLOTS];

__device__ __half g_a[(size_t)NSLOTS * D_DIM];   // x gathered, fp16
__device__ __half g_h[(size_t)NSLOTS * F_DIM];   // gelu(fc), fp16
// transposed K-major fp16 weights: wfcT [E][F][D], wpjT [E][D][F]
__device__ __half g_wfc[(size_t)E_EXP * F_DIM * D_DIM];
__device__ __half g_wpj[(size_t)E_EXP * D_DIM * F_DIM];

// ------------------------------------------------------------------ helpers
__device__ __forceinline__ uint32_t smem_u32(const void* p) {
    uint32_t a;
    asm("{ .reg .u64 t; cvta.to.shared.u64 t, %1; cvt.u32.u64 %0, t; }" : "=r"(a) : "l"(p));
    return a;
}
__device__ __forceinline__ void cp16(uint32_t s, const void* g) {
    asm volatile("cp.async.cg.shared.global [%0], [%1], 16;" :: "r"(s), "l"(g));
}
#define CP_COMMIT() asm volatile("cp.async.commit_group;" ::: "memory")

__device__ __forceinline__ void ldsm4(uint32_t r[4], uint32_t addr) {
    asm volatile("ldmatrix.sync.aligned.m8n8.x4.shared.b16 {%0,%1,%2,%3}, [%4];"
                 : "=r"(r[0]), "=r"(r[1]), "=r"(r[2]), "=r"(r[3]) : "r"(addr));
}
__device__ __forceinline__ void mma16816(float c[4], const uint32_t a[4],
                                         uint32_t b0, uint32_t b1) {
    asm volatile("mma.sync.aligned.m16n8k16.row.col.f32.f16.f16.f32 "
                 "{%0,%1,%2,%3}, {%4,%5,%6,%7}, {%8,%9}, {%0,%1,%2,%3};"
                 : "+f"(c[0]), "+f"(c[1]), "+f"(c[2]), "+f"(c[3])
                 : "r"(a[0]), "r"(a[1]), "r"(a[2]), "r"(a[3]), "r"(b0), "r"(b1));
}

// ------------------------------------------------------------------ merged prep:
// blocks [0, 512): fused router + slot fill + x->fp16 (one warp per token)
// blocks [512, ...): weight transpose+convert for BOTH weight tensors
#define RT_BLOCKS 512
#define CW_FC_TILES 18432                 // (F/32)*(D/32)*E = 96*24*8
#define CW_PJ_TILES 18432                 // (D/32)*(F/32)*E

__global__ void k_prep(const float* __restrict__ x,  const float* __restrict__ rw,
                       const float* __restrict__ wfc, const float* __restrict__ wpj)
{
    if (blockIdx.x < RT_BLOCKS) {
        // -------- router part --------
        __shared__ float s_rw[E_EXP * D_DIM];
        for (int i = threadIdx.x; i < E_EXP * D_DIM; i += blockDim.x) s_rw[i] = rw[i];
        __syncthreads();
        int warp = threadIdx.x >> 5, lane = threadIdx.x & 31;
        int t = blockIdx.x * 8 + warp;
        if (t >= T_TOKENS) return;

        const float* xrow = x + (size_t)t * D_DIM;
        float xr[24];
#pragma unroll
        for (int i = 0; i < 24; i++) xr[i] = xrow[lane + 32 * i];

        float logit[E_EXP];
#pragma unroll
        for (int e = 0; e < E_EXP; e++) {
            float p = 0.f;
#pragma unroll
            for (int i = 0; i < 24; i++) p = fmaf(xr[i], s_rw[e * D_DIM + lane + 32 * i], p);
#pragma unroll
            for (int o = 16; o; o >>= 1) p += __shfl_xor_sync(0xffffffffu, p, o);
            logit[e] = p;
        }
        int slot0 = 0, slot1 = 0;
        if (lane == 0) {
            int e0 = 0; float v0 = logit[0];
#pragma unroll
            for (int e = 1; e < E_EXP; e++) if (logit[e] > v0) { v0 = logit[e]; e0 = e; }
            int e1 = 0; float v1 = -3.0e38f;
#pragma unroll
            for (int e = 0; e < E_EXP; e++) {
                if (e == e0) continue;
                if (logit[e] > v1) { v1 = logit[e]; e1 = e; }
            }
            float ex = expf(v1 - v0);
            float inv = 1.f / (1.f + ex);
            slot0 = e0 * EXP_CAP + atomicAdd(&g_fill[e0], 1);
            slot1 = e1 * EXP_CAP + atomicAdd(&g_fill[e1], 1);
            g_slot_token[slot0] = t;  g_slot_w[slot0] = inv;
            g_slot_token[slot1] = t;  g_slot_w[slot1] = ex * inv;
        }
        slot0 = __shfl_sync(0xffffffffu, slot0, 0);
        slot1 = __shfl_sync(0xffffffffu, slot1, 0);
#pragma unroll
        for (int i = 0; i < 24; i++) {
            __half h = __float2half(xr[i]);
            int c = lane + 32 * i;
            g_a[(size_t)slot0 * D_DIM + c] = h;
            g_a[(size_t)slot1 * D_DIM + c] = h;
        }
    } else {
        // -------- weight convert part (32x32 transpose tiles, 256 threads) --------
        __shared__ float tile[32][33];
        const int b = blockIdx.x - RT_BLOCKS;
        const bool second = (b >= CW_FC_TILES);
        const int t = second ? b - CW_FC_TILES : b;
        const int K = second ? F_DIM : D_DIM;
        const int N = second ? D_DIM : F_DIM;
        const int XT = N / 32, YT = K / 32;
        const int xaugust = t % XT, y = (t / XT) % YT, e = t / (XT * YT);
        const float* src = second ? wpj : wfc;
        __half* dst = second ? g_wpj : g_wfc;
        const int tx = threadIdx.x & 31, ty = threadIdx.x >> 5;

        int n0 = xaugust * 32, k0 = y * 32;
        const float* s = src + (size_t)e * K * N;
#pragma unroll
        for (int dy = 0; dy < 32; dy += 8)
            tile[ty + dy][tx] = s[(size_t)(k0 + ty + dy) * N + n0 + tx];
        __syncthreads();
        size_t db = (size_t)e * N * K;
#pragma unroll
        for (int dy = 0; dy < 32; dy += 8) {
            int n = n0 + ty + dy, k = k0 + tx;
            dst[db + (size_t)n * K + k] = __float2half(tile[tx][ty + dy]);
        }
    }
}

// ------------------------------------------------------------------ mma.sync grouped GEMM
// CTA 128x64, 4 warps (warp tile 64x32), single-pass fp16.
// 4 stages x 24KB (96KB smem, 2 CTAs/SM); TWO K64 chunks per barrier+wait
// (512 MMAs between syncs). Fragment double-buffering across the 8 k16 steps.
// gemm2 uses split-K x2 (atomicAdd combine).
#define OFF_B 16384
#define STAGE_BYTES 24576
#define N_STAGES 4
#define GEMM_SMEM (N_STAGES * STAGE_BYTES + 1024)

__device__ __forceinline__ uint32_t sw_addr(uint32_t tbase, int row, int byte) {
    uint32_t b = (uint32_t)(row * 128 + byte);
    return tbase + (b ^ ((b >> 3) & 0x70));
}

template <bool IS_FC>
__global__ __launch_bounds__(128, 2)
void k_mma_gemm(const float* __restrict__ bias, float* __restrict__ out)
{
    constexpr int Kdim = IS_FC ? D_DIM : F_DIM;
    constexpr int Ndim = IS_FC ? F_DIM : D_DIM;
    constexpr int NC   = IS_FC ? (Kdim / 64) : (Kdim / 64 / 2);   // K64 chunks (12 both)
    constexpr int NP   = NC / 2;                                   // chunk pairs

    const int zz     = blockIdx.z;
    const int e      = IS_FC ? zz : (zz >> 1);
    const int ksplit = IS_FC ? 0 : (zz & 1);
    const int kbase  = ksplit * NC;

    const int cnt = g_fill[e];
    const int off = e * EXP_CAP;
    const int m0  = blockIdx.x * 128;
    if (m0 >= cnt) return;
    const int n0 = blockIdx.y * 64;

    const __half* Asrc = IS_FC ? g_a : g_h;
    const __half* Bsrc = (IS_FC ? g_wfc : g_wpj) + (size_t)e * Ndim * Kdim;

    extern __shared__ char smem_raw[];
    const uint32_t sbase = (smem_u32(smem_raw) + 1023) & ~1023u;

    const int tid = threadIdx.x;
    const int wid = tid >> 5, lid = tid & 31;
    const int wm = (wid >> 1) * 64;
    const int wn = (wid & 1) * 32;
    const int c16 = tid & 7;
    const int r0  = tid >> 3;

    uint32_t aOff[8];
#pragma unroll
    for (int j = 0; j < 8; j++) {
        int gr = off + min(m0 + r0 + j * 16, cnt - 1);
        aOff[j] = (uint32_t)gr * (uint32_t)(Kdim * 2) + (uint32_t)(c16 * 16);
    }
    const uint32_t bOff0 = (uint32_t)(n0 + r0) * (uint32_t)(Kdim * 2) + (uint32_t)(c16 * 16);
    uint32_t sb0 = (uint32_t)(r0 * 128 + c16 * 16);
    const uint32_t sSw0 = sb0 ^ ((sb0 >> 3) & 0x70);

    const char* aSrcC = (const char*)Asrc;
    const char* bSrcC = (const char*)Bsrc;

    auto load_chunk = [&](int chunk, int st) {
        uint32_t sb = sbase + st * STAGE_BYTES;
        uint32_t ko = (uint32_t)(kbase + chunk) * 128u;
#pragma unroll
        for (int j = 0; j < 8; j++)
            cp16(sb + sSw0 + j * 2048u, aSrcC + aOff[j] + ko);
#pragma unroll
        for (int j = 0; j < 4; j++)
            cp16(sb + OFF_B + sSw0 + j * 2048u,
                 bSrcC + bOff0 + j * (uint32_t)(16 * Kdim * 2) + ko);
        CP_COMMIT();
    };

    float acc[4][4][4];
#pragma unroll
    for (int i = 0; i < 4; i++)
#pragma unroll
        for (int j = 0; j < 4; j++)
#pragma unroll
            for (int c = 0; c < 4; c++) acc[i][j][c] = 0.f;

    // prologue: pairs 0 and 1 in flight (4 chunks, 4 commit groups)
    load_chunk(0, 0);
    load_chunk(1, 1);
    load_chunk(2, 2);
    load_chunk(3, 3);

    const int aRow = lid & 15;
    const int aHi16 = ((lid >> 4) & 1) * 16;
    const int bRowSel = ((lid >> 4) & 1) * 8 + (lid & 7);
    const int bHi16 = ((lid >> 3) & 1) * 16;

    uint32_t ah[2][4][4], bh[2][2][4];

    for (int p = 0; p < NP; p++) {
        const uint32_t sA = sbase + ((2 * p)     & 3) * STAGE_BYTES;
        const uint32_t sB = sbase + ((2 * p + 1) & 3) * STAGE_BYTES;

        // ensure pair p landed (outstanding allowed: pair p+1 = 2 groups)
        if (p < NP - 1) asm volatile("cp.async.wait_group 2;" ::: "memory");
        else            asm volatile("cp.async.wait_group 0;" ::: "memory");
        __syncthreads();   // also confirms pair p-1's stages fully consumed last iter

        auto ld_frags = [&](int buf, int qs) {       // qs in 0..7 across the pair
            const uint32_t tA = (qs < 4) ? sA : sB;
            const uint32_t tB = tA + OFF_B;
            const int q = qs & 3;
#pragma unroll
            for (int mi = 0; mi < 4; mi++) {
                uint32_t adr = sw_addr(tA, wm + mi * 16 + aRow, q * 32 + aHi16);
                ldsm4(ah[buf][mi], adr);
            }
#pragma unroll
            for (int nj2 = 0; nj2 < 2; nj2++) {
                uint32_t adr = sw_addr(tB, wn + nj2 * 16 + bRowSel, q * 32 + bHi16);
                ldsm4(bh[buf][nj2], adr);
            }
        };

        ld_frags(0, 0);
#pragma unroll
        for (int qs = 0; qs < 8; qs++) {
            if (qs < 7) ld_frags((qs + 1) & 1, qs + 1);
            const int b = qs & 1;
#pragma unroll
            for (int mi = 0; mi < 4; mi++)
#pragma unroll
                for (int nj = 0; nj < 4; nj++) {
                    uint32_t b0 = bh[b][nj >> 1][(nj & 1) * 2];
                    uint32_t b1 = bh[b][nj >> 1][(nj & 1) * 2 + 1];
                    mma16816(acc[mi][nj], ah[b][mi], b0, b1);
                }
        }

        __syncthreads();   // all warps done reading pair p's stages
        if (p + 2 < NP) {  // refill those stages with pair p+2
            load_chunk(2 * p + 4, (2 * p)     & 3);
            load_chunk(2 * p + 5, (2 * p + 1) & 3);
        }
    }

    // ---- epilogue ----
    const float* bp = bias + (size_t)e * Ndim + n0;
    const bool addb = IS_FC || (ksplit == 0);
    const int rbase = wm + (lid >> 2);
    const int cquad = (lid & 3) * 2;

#pragma unroll
    for (int mi = 0; mi < 4; mi++) {
#pragma unroll
        for (int half = 0; half < 2; half++) {
            const int row = rbase + mi * 16 + half * 8;
            const int m = m0 + row;
            if (m >= cnt) continue;
            const int slot = off + m;
            int tok = 0; float wgt = 0.f;
            if (!IS_FC) { tok = g_slot_token[slot]; wgt = g_slot_w[slot]; }
#pragma unroll
            for (int nj = 0; nj < 4; nj++) {
                const int col = wn + nj * 8 + cquad;
                float b0 = addb ? bp[col] : 0.f;
                float b1 = addb ? bp[col + 1] : 0.f;
                float v0 = acc[mi][nj][half * 2 + 0] + b0;
                float v1 = acc[mi][nj][half * 2 + 1] + b1;
                if (IS_FC) {
                    float g0 = 0.5f * v0 * (1.f + erff(v0 * 0.70710678118654752f));
                    float g1 = 0.5f * v1 * (1.f + erff(v1 * 0.70710678118654752f));
                    __half h0 = __float2half(g0);
                    __half h1 = __float2half(g1);
                    size_t idx = (size_t)slot * Ndim + n0 + col;
                    *(uint32_t*)(g_h + idx) =
                        (uint32_t)__half_as_ushort(h0) |
                        ((uint32_t)__half_as_ushort(h1) << 16);
                } else {
                    float* op = out + (size_t)tok * D_DIM + n0 + col;
                    atomicAdd(op + 0, v0 * wgt);
                    atomicAdd(op + 1, v1 * wgt);
                }
            }
        }
    }
}

// ------------------------------------------------------------------ launch
extern "C" void kernel_launch(void* const* d_in, const int* in_sizes, int n_in,
                              void* d_out, int out_size)
{
    const float* x      = (const float*)d_in[0];
    const float* rw     = (const float*)d_in[1];
    const float* w_fc   = (const float*)d_in[2];
    const float* b_fc   = (const float*)d_in[3];
    const float* w_proj = (const float*)d_in[4];
    const float* b_proj = (const float*)d_in[5];
    float* out = (float*)d_out;

    cudaFuncSetAttribute(k_mma_gemm<true>,  cudaFuncAttributeMaxDynamicSharedMemorySize, GEMM_SMEM);
    cudaFuncSetAttribute(k_mma_gemm<false>, cudaFuncAttributeMaxDynamicSharedMemorySize, GEMM_SMEM);

    cudaMemsetAsync(out, 0, (size_t)out_size * sizeof(float));              // #1
    void* pfill = nullptr;
    cudaGetSymbolAddress(&pfill, g_fill);
    cudaMemsetAsync(pfill, 0, E_EXP * sizeof(int));                         // #2

    // merged router + both weight conversions (router blocks first)
    k_prep<<<RT_BLOCKS + CW_FC_TILES + CW_PJ_TILES, 256>>>(x, rw, w_fc, w_proj);  // #3

    // gemm1: CTA tile 128x64
    k_mma_gemm<true ><<<dim3(EXP_CAP / 128, F_DIM / 64, E_EXP), 128, GEMM_SMEM>>>(b_fc, nullptr);      // #4
    // gemm2: split-K x2 -> grid.z = 2*experts   (profiled slot this round)
    k_mma_gemm<false><<<dim3(EXP_CAP / 128, D_DIM / 64, E_EXP * 2), 128, GEMM_SMEM>>>(b_proj, out);    // #5
}

// round 15
// speedup vs baseline: 1.1756x; 1.1756x over previous
#include <cuda_runtime.h>
#include <cuda_fp16.h>
#include <math.h>
#include <stdint.h>

#define T_TOKENS 4096
#define D_DIM    768
#define F_DIM    3072
#define E_EXP    8
#define EXP_CAP  4096
#define NSLOTS   (E_EXP * EXP_CAP)

// ------------------------------------------------------------------ scratch
__device__ int   g_fill[E_EXP];          // zeroed by memset each call
__device__ int   g_slot_token[NSLOTS];
__device__ float g_slot_w[NSLOTS];

__device__ __half g_a[(size_t)NSLOTS * D_DIM];   // x gathered, fp16
__device__ __half g_h[(size_t)NSLOTS * F_DIM];   // gelu(fc), fp16
// transposed K-major fp16 weights: wfcT [E][F][D], wpjT [E][D][F]
__device__ __half g_wfc[(size_t)E_EXP * F_DIM * D_DIM];
__device__ __half g_wpj[(size_t)E_EXP * D_DIM * F_DIM];

// ------------------------------------------------------------------ helpers
__device__ __forceinline__ uint32_t smem_u32(const void* p) {
    uint32_t a;
    asm("{ .reg .u64 t; cvta.to.shared.u64 t, %1; cvt.u32.u64 %0, t; }" : "=r"(a) : "l"(p));
    return a;
}
__device__ __forceinline__ void cp16(uint32_t s, const void* g) {
    asm volatile("cp.async.cg.shared.global [%0], [%1], 16;" :: "r"(s), "l"(g));
}
#define CP_COMMIT() asm volatile("cp.async.commit_group;" ::: "memory")

__device__ __forceinline__ void ldsm4(uint32_t r[4], uint32_t addr) {
    asm volatile("ldmatrix.sync.aligned.m8n8.x4.shared.b16 {%0,%1,%2,%3}, [%4];"
                 : "=r"(r[0]), "=r"(r[1]), "=r"(r[2]), "=r"(r[3]) : "r"(addr));
}
__device__ __forceinline__ void mma16816(float c[4], const uint32_t a[4],
                                         uint32_t b0, uint32_t b1) {
    asm volatile("mma.sync.aligned.m16n8k16.row.col.f32.f16.f16.f32 "
                 "{%0,%1,%2,%3}, {%4,%5,%6,%7}, {%8,%9}, {%0,%1,%2,%3};"
                 : "+f"(c[0]), "+f"(c[1]), "+f"(c[2]), "+f"(c[3])
                 : "r"(a[0]), "r"(a[1]), "r"(a[2]), "r"(a[3]), "r"(b0), "r"(b1));
}

// ------------------------------------------------------------------ weight convert
// transpose: src [E][K][N] fp32 -> dst [E][N][K] fp16
__global__ void k_convw(const float* __restrict__ src, int K, int N, int which) {
    __shared__ float tile[32][33];
    __half* dst = which ? g_wpj : g_wfc;
    int e = blockIdx.z;
    int n0 = blockIdx.x * 32, k0 = blockIdx.y * 32;
    const float* s = src + (size_t)e * K * N;
#pragma unroll
    for (int dy = 0; dy < 32; dy += 8)
        tile[threadIdx.y + dy][threadIdx.x] =
            s[(size_t)(k0 + threadIdx.y + dy) * N + n0 + threadIdx.x];
    __syncthreads();
    size_t db = (size_t)e * N * K;
#pragma unroll
    for (int dy = 0; dy < 32; dy += 8) {
        int n = n0 + threadIdx.y + dy, k = k0 + threadIdx.x;
        dst[db + (size_t)n * K + k] = __float2half(tile[threadIdx.x][threadIdx.y + dy]);
    }
}

// ------------------------------------------------------------------ fused router + slot fill + x->fp16
__global__ void k_router(const float* __restrict__ x, const float* __restrict__ rw) {
    __shared__ float s_rw[E_EXP * D_DIM];
    for (int i = threadIdx.x; i < E_EXP * D_DIM; i += blockDim.x) s_rw[i] = rw[i];
    __syncthreads();
    int warp = threadIdx.x >> 5, lane = threadIdx.x & 31;
    int t = blockIdx.x * 8 + warp;
    if (t >= T_TOKENS) return;

    const float* xrow = x + (size_t)t * D_DIM;
    float xr[24];
#pragma unroll
    for (int i = 0; i < 24; i++) xr[i] = xrow[lane + 32 * i];

    float logit[E_EXP];
#pragma unroll
    for (int e = 0; e < E_EXP; e++) {
        float p = 0.f;
#pragma unroll
        for (int i = 0; i < 24; i++) p = fmaf(xr[i], s_rw[e * D_DIM + lane + 32 * i], p);
#pragma unroll
        for (int o = 16; o; o >>= 1) p += __shfl_xor_sync(0xffffffffu, p, o);
        logit[e] = p;
    }
    int slot0 = 0, slot1 = 0;
    if (lane == 0) {
        int e0 = 0; float v0 = logit[0];
#pragma unroll
        for (int e = 1; e < E_EXP; e++) if (logit[e] > v0) { v0 = logit[e]; e0 = e; }
        int e1 = 0; float v1 = -3.0e38f;
#pragma unroll
        for (int e = 0; e < E_EXP; e++) {
            if (e == e0) continue;
            if (logit[e] > v1) { v1 = logit[e]; e1 = e; }
        }
        float ex = expf(v1 - v0);
        float inv = 1.f / (1.f + ex);
        slot0 = e0 * EXP_CAP + atomicAdd(&g_fill[e0], 1);
        slot1 = e1 * EXP_CAP + atomicAdd(&g_fill[e1], 1);
        g_slot_token[slot0] = t;  g_slot_w[slot0] = inv;
        g_slot_token[slot1] = t;  g_slot_w[slot1] = ex * inv;
    }
    slot0 = __shfl_sync(0xffffffffu, slot0, 0);
    slot1 = __shfl_sync(0xffffffffu, slot1, 0);

#pragma unroll
    for (int i = 0; i < 24; i++) {
        __half h = __float2half(xr[i]);
        int c = lane + 32 * i;
        g_a[(size_t)slot0 * D_DIM + c] = h;
        g_a[(size_t)slot1 * D_DIM + c] = h;
    }
}

// ------------------------------------------------------------------ mma.sync grouped GEMM
// CTA 128x64, 4 warps (warp tile 64x32), single-pass fp16 A*B.
// Chunk = K64. Stage 24KB: A 128x128B + B 64x128B, both SW128 K-major.
// 3 stages (72KB) -> 3 CTAs/SM. Fragment double-buffering across k16 steps.
// gemm2 uses split-K x2 (atomicAdd combine).
#define OFF_B 16384
#define STAGE_BYTES 24576
#define N_STAGES 3
#define GEMM_SMEM (N_STAGES * STAGE_BYTES + 1024)

__device__ __forceinline__ uint32_t sw_addr(uint32_t tbase, int row, int byte) {
    uint32_t b = (uint32_t)(row * 128 + byte);
    return tbase + (b ^ ((b >> 3) & 0x70));
}

template <bool IS_FC>
__global__ __launch_bounds__(128, 3)
void k_mma_gemm(const float* __restrict__ bias, float* __restrict__ out)
{
    constexpr int Kdim = IS_FC ? D_DIM : F_DIM;
    constexpr int Ndim = IS_FC ? F_DIM : D_DIM;
    constexpr int NC   = IS_FC ? (Kdim / 64) : (Kdim / 64 / 2);   // K64 chunks this CTA

    const int zz     = blockIdx.z;
    const int e      = IS_FC ? zz : (zz >> 1);
    const int ksplit = IS_FC ? 0 : (zz & 1);
    const int kbase  = ksplit * NC;

    const int cnt = g_fill[e];
    const int off = e * EXP_CAP;
    const int m0  = blockIdx.x * 128;
    if (m0 >= cnt) return;
    const int n0 = blockIdx.y * 64;

    const __half* Asrc = IS_FC ? g_a : g_h;
    const __half* Bsrc = (IS_FC ? g_wfc : g_wpj) + (size_t)e * Ndim * Kdim;

    extern __shared__ char smem_raw[];
    const uint32_t sbase = (smem_u32(smem_raw) + 1023) & ~1023u;

    const int tid = threadIdx.x;
    const int wid = tid >> 5, lid = tid & 31;
    const int wm = (wid >> 1) * 64;     // 2x2 warp grid over 128x64
    const int wn = (wid & 1) * 32;

    // ---- load mappings (register diet):
    // smem swizzled offsets are linear in j (+16 rows -> +2048, row&7 invariant)
    // B global offsets are linear in j (no clamp); A offsets clamped -> array.
    const int c16 = tid & 7;
    const int r0  = tid >> 3;
    uint32_t aOff[8];
#pragma unroll
    for (int j = 0; j < 8; j++) {
        int gr = off + min(m0 + r0 + j * 16, cnt - 1);
        aOff[j] = (uint32_t)gr * (uint32_t)(Kdim * 2) + (uint32_t)(c16 * 16);
    }
    const uint32_t bOff0 = (uint32_t)(n0 + r0) * (uint32_t)(Kdim * 2) + (uint32_t)(c16 * 16);
    uint32_t sb0 = (uint32_t)(r0 * 128 + c16 * 16);
    const uint32_t sSw0 = sb0 ^ ((sb0 >> 3) & 0x70);     // + j*2048 for row j*16

    const char* aSrcC = (const char*)Asrc;
    const char* bSrcC = (const char*)Bsrc;

    auto load_chunk = [&](int chunk, int st) {
        uint32_t sb = sbase + st * STAGE_BYTES;
        uint32_t ko = (uint32_t)(kbase + chunk) * 128u;   // 64 fp16 = 128B
#pragma unroll
        for (int j = 0; j < 8; j++)
            cp16(sb + sSw0 + j * 2048u, aSrcC + aOff[j] + ko);
#pragma unroll
        for (int j = 0; j < 4; j++)
            cp16(sb + OFF_B + sSw0 + j * 2048u,
                 bSrcC + bOff0 + j * (uint32_t)(16 * Kdim * 2) + ko);
        CP_COMMIT();
    };

    float acc[4][4][4];
#pragma unroll
    for (int i = 0; i < 4; i++)
#pragma unroll
        for (int j = 0; j < 4; j++)
#pragma unroll
            for (int c = 0; c < 4; c++) acc[i][j][c] = 0.f;

    load_chunk(0, 0);
    load_chunk(1, 1);

    // ldmatrix lane addressing
    const int aRow = lid & 15;
    const int aHi16 = ((lid >> 4) & 1) * 16;
    const int bRowSel = ((lid >> 4) & 1) * 8 + (lid & 7);
    const int bHi16 = ((lid >> 3) & 1) * 16;

    // double-buffered fragments
    uint32_t ah[2][4][4], bh[2][2][4];

    for (int k = 0; k < NC; k++) {
        const int st = k % N_STAGES;
        if (k < NC - 1) asm volatile("cp.async.wait_group 1;" ::: "memory");
        else            asm volatile("cp.async.wait_group 0;" ::: "memory");
        __syncthreads();
        if (k + 2 < NC) load_chunk(k + 2, (k + 2) % N_STAGES);

        const uint32_t tA = sbase + st * STAGE_BYTES;
        const uint32_t tB = tA + OFF_B;

        auto ld_frags = [&](int buf, int q) {
#pragma unroll
            for (int mi = 0; mi < 4; mi++) {
                uint32_t adr = sw_addr(tA, wm + mi * 16 + aRow, q * 32 + aHi16);
                ldsm4(ah[buf][mi], adr);
            }
#pragma unroll
            for (int nj2 = 0; nj2 < 2; nj2++) {
                uint32_t adr = sw_addr(tB, wn + nj2 * 16 + bRowSel, q * 32 + bHi16);
                ldsm4(bh[buf][nj2], adr);
            }
        };

        ld_frags(0, 0);
#pragma unroll
        for (int q = 0; q < 4; q++) {
            if (q < 3) ld_frags((q + 1) & 1, q + 1);   // prefetch next k16 frags
            const int b = q & 1;
#pragma unroll
            for (int mi = 0; mi < 4; mi++)
#pragma unroll
                for (int nj = 0; nj < 4; nj++) {
                    uint32_t b0 = bh[b][nj >> 1][(nj & 1) * 2];
                    uint32_t b1 = bh[b][nj >> 1][(nj & 1) * 2 + 1];
                    mma16816(acc[mi][nj], ah[b][mi], b0, b1);
                }
        }
    }

    // ---- epilogue ----
    const float* bp = bias + (size_t)e * Ndim + n0;
    const bool addb = IS_FC || (ksplit == 0);
    const int rbase = wm + (lid >> 2);
    const int cquad = (lid & 3) * 2;

#pragma unroll
    for (int mi = 0; mi < 4; mi++) {
#pragma unroll
        for (int half = 0; half < 2; half++) {
            const int row = rbase + mi * 16 + half * 8;
            const int m = m0 + row;
            if (m >= cnt) continue;
            const int slot = off + m;
            int tok = 0; float wgt = 0.f;
            if (!IS_FC) { tok = g_slot_token[slot]; wgt = g_slot_w[slot]; }
#pragma unroll
            for (int nj = 0; nj < 4; nj++) {
                const int col = wn + nj * 8 + cquad;
                float b0 = addb ? bp[col] : 0.f;
                float b1 = addb ? bp[col + 1] : 0.f;
                float v0 = acc[mi][nj][half * 2 + 0] + b0;
                float v1 = acc[mi][nj][half * 2 + 1] + b1;
                if (IS_FC) {
                    float g0 = 0.5f * v0 * (1.f + erff(v0 * 0.70710678118654752f));
                    float g1 = 0.5f * v1 * (1.f + erff(v1 * 0.70710678118654752f));
                    __half h0 = __float2half(g0);
                    __half h1 = __float2half(g1);
                    size_t idx = (size_t)slot * Ndim + n0 + col;
                    *(uint32_t*)(g_h + idx) =
                        (uint32_t)__half_as_ushort(h0) |
                        ((uint32_t)__half_as_ushort(h1) << 16);
                } else {
                    float* op = out + (size_t)tok * D_DIM + n0 + col;
                    atomicAdd(op + 0, v0 * wgt);
                    atomicAdd(op + 1, v1 * wgt);
                }
            }
        }
    }
}

// ------------------------------------------------------------------ launch
// Fork weight conversions onto side streams so they overlap with the router
// (convw_fc) and with gemm1 (convw_pj). Event edges make this graph-capturable.
extern "C" void kernel_launch(void* const* d_in, const int* in_sizes, int n_in,
                              void* d_out, int out_size)
{
    const float* x      = (const float*)d_in[0];
    const float* rw     = (const float*)d_in[1];
    const float* w_fc   = (const float*)d_in[2];
    const float* b_fc   = (const float*)d_in[3];
    const float* w_proj = (const float*)d_in[4];
    const float* b_proj = (const float*)d_in[5];
    float* out = (float*)d_out;

    static cudaStream_t s1 = nullptr, s2 = nullptr;
    static cudaEvent_t evFork = nullptr, evW1 = nullptr, evW2 = nullptr;
    if (s1 == nullptr) {
        cudaStreamCreateWithFlags(&s1, cudaStreamNonBlocking);
        cudaStreamCreateWithFlags(&s2, cudaStreamNonBlocking);
        cudaEventCreateWithFlags(&evFork, cudaEventDisableTiming);
        cudaEventCreateWithFlags(&evW1,   cudaEventDisableTiming);
        cudaEventCreateWithFlags(&evW2,   cudaEventDisableTiming);
    }

    cudaFuncSetAttribute(k_mma_gemm<true>,  cudaFuncAttributeMaxDynamicSharedMemorySize, GEMM_SMEM);
    cudaFuncSetAttribute(k_mma_gemm<false>, cudaFuncAttributeMaxDynamicSharedMemorySize, GEMM_SMEM);

    cudaMemsetAsync(out, 0, (size_t)out_size * sizeof(float));
    void* pfill = nullptr;
    cudaGetSymbolAddress(&pfill, g_fill);
    cudaMemsetAsync(pfill, 0, E_EXP * sizeof(int));

    // fork
    cudaEventRecord(evFork, 0);
    cudaStreamWaitEvent(s1, evFork, 0);
    cudaStreamWaitEvent(s2, evFork, 0);

    dim3 bw(32, 8);
    k_convw<<<dim3(F_DIM / 32, D_DIM / 32, E_EXP), bw, 0, s1>>>(w_fc,   D_DIM, F_DIM, 0);
    cudaEventRecord(evW1, s1);
    k_convw<<<dim3(D_DIM / 32, F_DIM / 32, E_EXP), bw, 0, s2>>>(w_proj, F_DIM, D_DIM, 1);
    cudaEventRecord(evW2, s2);

    // router runs concurrently with both conversions on the main stream
    k_router<<<T_TOKENS / 8, 256>>>(x, rw);

    // gemm1 needs wfc + router
    cudaStreamWaitEvent(0, evW1, 0);
    k_mma_gemm<true ><<<dim3(EXP_CAP / 128, F_DIM / 64, E_EXP), 128, GEMM_SMEM>>>(b_fc, nullptr);

    // gemm2 needs gemm1 + wpj (wpj conversion overlapped with gemm1)
    cudaStreamWaitEvent(0, evW2, 0);
    k_mma_gemm<false><<<dim3(EXP_CAP / 128, D_DIM / 64, E_EXP * 2), 128, GEMM_SMEM>>>(b_proj, out);
}

// round 16
// speedup vs baseline: 1.2308x; 1.0469x over previous
#include <cuda_runtime.h>
#include <cuda_fp16.h>
#include <math.h>
#include <stdint.h>

#define T_TOKENS 4096
#define D_DIM    768
#define F_DIM    3072
#define E_EXP    8
#define EXP_CAP  4096
#define NSLOTS   (E_EXP * EXP_CAP)

// ------------------------------------------------------------------ scratch
__device__ int   g_fill[E_EXP];          // zeroed by memset each call
__device__ int   g_slot_token[NSLOTS];
__device__ float g_slot_w[NSLOTS];

__device__ __half g_a[(size_t)NSLOTS * D_DIM];   // x gathered, fp16
__device__ __half g_h[(size_t)NSLOTS * F_DIM];   // gelu(fc), fp16
// transposed K-major fp16 weights: wfcT [E][F][D], wpjT [E][D][F]
__device__ __half g_wfc[(size_t)E_EXP * F_DIM * D_DIM];
__device__ __half g_wpj[(size_t)E_EXP * D_DIM * F_DIM];

// ------------------------------------------------------------------ helpers
__device__ __forceinline__ uint32_t smem_u32(const void* p) {
    uint32_t a;
    asm("{ .reg .u64 t; cvta.to.shared.u64 t, %1; cvt.u32.u64 %0, t; }" : "=r"(a) : "l"(p));
    return a;
}
__device__ __forceinline__ void cp16(uint32_t s, const void* g) {
    asm volatile("cp.async.cg.shared.global [%0], [%1], 16;" :: "r"(s), "l"(g));
}
#define CP_COMMIT() asm volatile("cp.async.commit_group;" ::: "memory")

__device__ __forceinline__ void ldsm4(uint32_t r[4], uint32_t addr) {
    asm volatile("ldmatrix.sync.aligned.m8n8.x4.shared.b16 {%0,%1,%2,%3}, [%4];"
                 : "=r"(r[0]), "=r"(r[1]), "=r"(r[2]), "=r"(r[3]) : "r"(addr));
}
__device__ __forceinline__ void mma16816(float c[4], const uint32_t a[4],
                                         uint32_t b0, uint32_t b1) {
    asm volatile("mma.sync.aligned.m16n8k16.row.col.f32.f16.f16.f32 "
                 "{%0,%1,%2,%3}, {%4,%5,%6,%7}, {%8,%9}, {%0,%1,%2,%3};"
                 : "+f"(c[0]), "+f"(c[1]), "+f"(c[2]), "+f"(c[3])
                 : "r"(a[0]), "r"(a[1]), "r"(a[2]), "r"(a[3]), "r"(b0), "r"(b1));
}

// ------------------------------------------------------------------ weight convert (vectorized)
// transpose: src [E][K][N] fp32 -> dst [E][N][K] fp16, 64x64 tiles,
// float4 coalesced loads + uint4 (8xfp16) coalesced stores.
__global__ void k_convw(const float* __restrict__ src, int K, int N, int which) {
    __shared__ float tile[64][65];
    __half* dst = which ? g_wpj : g_wfc;
    const int e = blockIdx.z;
    const int n0 = blockIdx.x * 64, k0 = blockIdx.y * 64;
    const float* s = src + (size_t)e * K * N;
    const int t = threadIdx.x;                 // 256 threads
    const int r0 = t >> 4, c = t & 15;         // 16 float4 per 256B row

#pragma unroll
    for (int j = 0; j < 4; j++) {
        int row = r0 + j * 16;
        float4 v = *(const float4*)(s + (size_t)(k0 + row) * N + n0 + c * 4);
        tile[row][c * 4 + 0] = v.x;
        tile[row][c * 4 + 1] = v.y;
        tile[row][c * 4 + 2] = v.z;
        tile[row][c * 4 + 3] = v.w;
    }
    __syncthreads();

    const size_t db = (size_t)e * N * K;
#pragma unroll
    for (int j = 0; j < 2; j++) {
        int id = t + 256 * j;                  // 512 tasks: n-row x k8-group
        int n = id >> 3, g = id & 7;
        __align__(16) __half hbuf[8];
#pragma unroll
        for (int kk = 0; kk < 8; kk++)
            hbuf[kk] = __float2half(tile[g * 8 + kk][n]);
        *(uint4*)(dst + db + (size_t)(n0 + n) * K + k0 + g * 8) = *(const uint4*)hbuf;
    }
}

// ------------------------------------------------------------------ fused router + slot fill + x->fp16
__global__ void k_router(const float* __restrict__ x, const float* __restrict__ rw) {
    __shared__ float s_rw[E_EXP * D_DIM];
    for (int i = threadIdx.x; i < E_EXP * D_DIM; i += blockDim.x) s_rw[i] = rw[i];
    __syncthreads();
    int warp = threadIdx.x >> 5, lane = threadIdx.x & 31;
    int t = blockIdx.x * 8 + warp;
    if (t >= T_TOKENS) return;

    const float* xrow = x + (size_t)t * D_DIM;
    float xr[24];
#pragma unroll
    for (int i = 0; i < 24; i++) xr[i] = xrow[lane + 32 * i];

    float logit[E_EXP];
#pragma unroll
    for (int e = 0; e < E_EXP; e++) {
        float p = 0.f;
#pragma unroll
        for (int i = 0; i < 24; i++) p = fmaf(xr[i], s_rw[e * D_DIM + lane + 32 * i], p);
#pragma unroll
        for (int o = 16; o; o >>= 1) p += __shfl_xor_sync(0xffffffffu, p, o);
        logit[e] = p;
    }
    int slot0 = 0, slot1 = 0;
    if (lane == 0) {
        int e0 = 0; float v0 = logit[0];
#pragma unroll
        for (int e = 1; e < E_EXP; e++) if (logit[e] > v0) { v0 = logit[e]; e0 = e; }
        int e1 = 0; float v1 = -3.0e38f;
#pragma unroll
        for (int e = 0; e < E_EXP; e++) {
            if (e == e0) continue;
            if (logit[e] > v1) { v1 = logit[e]; e1 = e; }
        }
        float ex = expf(v1 - v0);
        float inv = 1.f / (1.f + ex);
        slot0 = e0 * EXP_CAP + atomicAdd(&g_fill[e0], 1);
        slot1 = e1 * EXP_CAP + atomicAdd(&g_fill[e1], 1);
        g_slot_token[slot0] = t;  g_slot_w[slot0] = inv;
        g_slot_token[slot1] = t;  g_slot_w[slot1] = ex * inv;
    }
    slot0 = __shfl_sync(0xffffffffu, slot0, 0);
    slot1 = __shfl_sync(0xffffffffu, slot1, 0);

#pragma unroll
    for (int i = 0; i < 24; i++) {
        __half h = __float2half(xr[i]);
        int c = lane + 32 * i;
        g_a[(size_t)slot0 * D_DIM + c] = h;
        g_a[(size_t)slot1 * D_DIM + c] = h;
    }
}

// ------------------------------------------------------------------ mma.sync grouped GEMM
// CTA 128x64, 4 warps (warp tile 64x32), single-pass fp16 A*B.
// Chunk = K64. Stage 24KB: A 128x128B + B 64x128B, both SW128 K-major.
// 3 stages (72KB) -> 3 CTAs/SM. Fragment double-buffering across k16 steps.
// gemm2 uses split-K x2 (atomicAdd combine).
#define OFF_B 16384
#define STAGE_BYTES 24576
#define N_STAGES 3
#define GEMM_SMEM (N_STAGES * STAGE_BYTES + 1024)

__device__ __forceinline__ uint32_t sw_addr(uint32_t tbase, int row, int byte) {
    uint32_t b = (uint32_t)(row * 128 + byte);
    return tbase + (b ^ ((b >> 3) & 0x70));
}

template <bool IS_FC>
__global__ __launch_bounds__(128, 3)
void k_mma_gemm(const float* __restrict__ bias, float* __restrict__ out)
{
    constexpr int Kdim = IS_FC ? D_DIM : F_DIM;
    constexpr int Ndim = IS_FC ? F_DIM : D_DIM;
    constexpr int NC   = IS_FC ? (Kdim / 64) : (Kdim / 64 / 2);   // K64 chunks this CTA

    const int zz     = blockIdx.z;
    const int e      = IS_FC ? zz : (zz >> 1);
    const int ksplit = IS_FC ? 0 : (zz & 1);
    const int kbase  = ksplit * NC;

    const int cnt = g_fill[e];
    const int off = e * EXP_CAP;
    const int m0  = blockIdx.x * 128;
    if (m0 >= cnt) return;
    const int n0 = blockIdx.y * 64;

    const __half* Asrc = IS_FC ? g_a : g_h;
    const __half* Bsrc = (IS_FC ? g_wfc : g_wpj) + (size_t)e * Ndim * Kdim;

    extern __shared__ char smem_raw[];
    const uint32_t sbase = (smem_u32(smem_raw) + 1023) & ~1023u;

    const int tid = threadIdx.x;
    const int wid = tid >> 5, lid = tid & 31;
    const int wm = (wid >> 1) * 64;     // 2x2 warp grid over 128x64
    const int wn = (wid & 1) * 32;

    const int c16 = tid & 7;
    const int r0  = tid >> 3;
    uint32_t aOff[8];
#pragma unroll
    for (int j = 0; j < 8; j++) {
        int gr = off + min(m0 + r0 + j * 16, cnt - 1);
        aOff[j] = (uint32_t)gr * (uint32_t)(Kdim * 2) + (uint32_t)(c16 * 16);
    }
    const uint32_t bOff0 = (uint32_t)(n0 + r0) * (uint32_t)(Kdim * 2) + (uint32_t)(c16 * 16);
    uint32_t sb0 = (uint32_t)(r0 * 128 + c16 * 16);
    const uint32_t sSw0 = sb0 ^ ((sb0 >> 3) & 0x70);     // + j*2048 for row j*16

    const char* aSrcC = (const char*)Asrc;
    const char* bSrcC = (const char*)Bsrc;

    auto load_chunk = [&](int chunk, int st) {
        uint32_t sb = sbase + st * STAGE_BYTES;
        uint32_t ko = (uint32_t)(kbase + chunk) * 128u;   // 64 fp16 = 128B
#pragma unroll
        for (int j = 0; j < 8; j++)
            cp16(sb + sSw0 + j * 2048u, aSrcC + aOff[j] + ko);
#pragma unroll
        for (int j = 0; j < 4; j++)
            cp16(sb + OFF_B + sSw0 + j * 2048u,
                 bSrcC + bOff0 + j * (uint32_t)(16 * Kdim * 2) + ko);
        CP_COMMIT();
    };

    float acc[4][4][4];
#pragma unroll
    for (int i = 0; i < 4; i++)
#pragma unroll
        for (int j = 0; j < 4; j++)
#pragma unroll
            for (int c = 0; c < 4; c++) acc[i][j][c] = 0.f;

    load_chunk(0, 0);
    load_chunk(1, 1);

    const int aRow = lid & 15;
    const int aHi16 = ((lid >> 4) & 1) * 16;
    const int bRowSel = ((lid >> 4) & 1) * 8 + (lid & 7);
    const int bHi16 = ((lid >> 3) & 1) * 16;

    uint32_t ah[2][4][4], bh[2][2][4];

    for (int k = 0; k < NC; k++) {
        const int st = k % N_STAGES;
        if (k < NC - 1) asm volatile("cp.async.wait_group 1;" ::: "memory");
        else            asm volatile("cp.async.wait_group 0;" ::: "memory");
        __syncthreads();
        if (k + 2 < NC) load_chunk(k + 2, (k + 2) % N_STAGES);

        const uint32_t tA = sbase + st * STAGE_BYTES;
        const uint32_t tB = tA + OFF_B;

        auto ld_frags = [&](int buf, int q) {
#pragma unroll
            for (int mi = 0; mi < 4; mi++) {
                uint32_t adr = sw_addr(tA, wm + mi * 16 + aRow, q * 32 + aHi16);
                ldsm4(ah[buf][mi], adr);
            }
#pragma unroll
            for (int nj2 = 0; nj2 < 2; nj2++) {
                uint32_t adr = sw_addr(tB, wn + nj2 * 16 + bRowSel, q * 32 + bHi16);
                ldsm4(bh[buf][nj2], adr);
            }
        };

        ld_frags(0, 0);
#pragma unroll
        for (int q = 0; q < 4; q++) {
            if (q < 3) ld_frags((q + 1) & 1, q + 1);   // prefetch next k16 frags
            const int b = q & 1;
#pragma unroll
            for (int mi = 0; mi < 4; mi++)
#pragma unroll
                for (int nj = 0; nj < 4; nj++) {
                    uint32_t b0 = bh[b][nj >> 1][(nj & 1) * 2];
                    uint32_t b1 = bh[b][nj >> 1][(nj & 1) * 2 + 1];
                    mma16816(acc[mi][nj], ah[b][mi], b0, b1);
                }
        }
    }

    // ---- epilogue ----
    const float* bp = bias + (size_t)e * Ndim + n0;
    const bool addb = IS_FC || (ksplit == 0);
    const int rbase = wm + (lid >> 2);
    const int cquad = (lid & 3) * 2;

#pragma unroll
    for (int mi = 0; mi < 4; mi++) {
#pragma unroll
        for (int half = 0; half < 2; half++) {
            const int row = rbase + mi * 16 + half * 8;
            const int m = m0 + row;
            if (m >= cnt) continue;
            const int slot = off + m;
            int tok = 0; float wgt = 0.f;
            if (!IS_FC) { tok = g_slot_token[slot]; wgt = g_slot_w[slot]; }
#pragma unroll
            for (int nj = 0; nj < 4; nj++) {
                const int col = wn + nj * 8 + cquad;
                float b0 = addb ? bp[col] : 0.f;
                float b1 = addb ? bp[col + 1] : 0.f;
                float v0 = acc[mi][nj][half * 2 + 0] + b0;
                float v1 = acc[mi][nj][half * 2 + 1] + b1;
                if (IS_FC) {
                    float g0 = 0.5f * v0 * (1.f + erff(v0 * 0.70710678118654752f));
                    float g1 = 0.5f * v1 * (1.f + erff(v1 * 0.70710678118654752f));
                    __half h0 = __float2half(g0);
                    __half h1 = __float2half(g1);
                    size_t idx = (size_t)slot * Ndim + n0 + col;
                    *(uint32_t*)(g_h + idx) =
                        (uint32_t)__half_as_ushort(h0) |
                        ((uint32_t)__half_as_ushort(h1) << 16);
                } else {
                    float* op = out + (size_t)tok * D_DIM + n0 + col;
                    atomicAdd(op + 0, v0 * wgt);
                    atomicAdd(op + 1, v1 * wgt);
                }
            }
        }
    }
}

// ------------------------------------------------------------------ launch
// Fork weight conversions onto side streams: convw_fc overlaps the router,
// convw_pj hides under gemm1. Event edges keep this graph-capturable.
extern "C" void kernel_launch(void* const* d_in, const int* in_sizes, int n_in,
                              void* d_out, int out_size)
{
    const float* x      = (const float*)d_in[0];
    const float* rw     = (const float*)d_in[1];
    const float* w_fc   = (const float*)d_in[2];
    const float* b_fc   = (const float*)d_in[3];
    const float* w_proj = (const float*)d_in[4];
    const float* b_proj = (const float*)d_in[5];
    float* out = (float*)d_out;

    static cudaStream_t s1 = nullptr, s2 = nullptr;
    static cudaEvent_t evFork = nullptr, evW1 = nullptr, evW2 = nullptr;
    if (s1 == nullptr) {
        cudaStreamCreateWithFlags(&s1, cudaStreamNonBlocking);
        cudaStreamCreateWithFlags(&s2, cudaStreamNonBlocking);
        cudaEventCreateWithFlags(&evFork, cudaEventDisableTiming);
        cudaEventCreateWithFlags(&evW1,   cudaEventDisableTiming);
        cudaEventCreateWithFlags(&evW2,   cudaEventDisableTiming);
    }

    cudaFuncSetAttribute(k_mma_gemm<true>,  cudaFuncAttributeMaxDynamicSharedMemorySize, GEMM_SMEM);
    cudaFuncSetAttribute(k_mma_gemm<false>, cudaFuncAttributeMaxDynamicSharedMemorySize, GEMM_SMEM);

    cudaMemsetAsync(out, 0, (size_t)out_size * sizeof(float));
    void* pfill = nullptr;
    cudaGetSymbolAddress(&pfill, g_fill);
    cudaMemsetAsync(pfill, 0, E_EXP * sizeof(int));

    // fork
    cudaEventRecord(evFork, 0);
    cudaStreamWaitEvent(s1, evFork, 0);
    cudaStreamWaitEvent(s2, evFork, 0);

    // vectorized 64x64-tile conversions
    k_convw<<<dim3(F_DIM / 64, D_DIM / 64, E_EXP), 256, 0, s1>>>(w_fc,   D_DIM, F_DIM, 0);
    cudaEventRecord(evW1, s1);
    k_convw<<<dim3(D_DIM / 64, F_DIM / 64, E_EXP), 256, 0, s2>>>(w_proj, F_DIM, D_DIM, 1);
    cudaEventRecord(evW2, s2);

    // router runs concurrently with both conversions on the main stream
    k_router<<<T_TOKENS / 8, 256>>>(x, rw);

    // gemm1 needs wfc + router
    cudaStreamWaitEvent(0, evW1, 0);
    k_mma_gemm<true ><<<dim3(EXP_CAP / 128, F_DIM / 64, E_EXP), 128, GEMM_SMEM>>>(b_fc, nullptr);

    // gemm2 needs gemm1 + wpj (wpj conversion overlapped with gemm1)
    cudaStreamWaitEvent(0, evW2, 0);
    k_mma_gemm<false><<<dim3(EXP_CAP / 128, D_DIM / 64, E_EXP * 2), 128, GEMM_SMEM>>>(b_proj, out);
}